// round 8
// baseline (speedup 1.0000x reference)
#include <cuda_runtime.h>
#include <cstdint>

#define NBLK   592              // 148 SMs x 4 blocks, one wave
#define NTHR   128
#define STAGES 5
#define CHUNK_BYTES 4096        // per array per stage
#define CHUNK_F4    (CHUNK_BYTES / 16)   // 256 float4
#define CHUNK_F     (CHUNK_BYTES / 4)    // 1024 floats

// Device scratch (no cudaMalloc). g_count wraps -> replay-deterministic.
__device__ float g_part[NBLK];
__device__ unsigned int g_count;

__device__ __forceinline__ uint32_t smem_u32(const void* p) {
    uint32_t a;
    asm("{ .reg .u64 t; cvta.to.shared.u64 t, %1; cvt.u32.u64 %0, t; }"
        : "=r"(a) : "l"(p));
    return a;
}

__device__ __forceinline__ void mbar_init(uint32_t mbar, uint32_t count) {
    asm volatile("mbarrier.init.shared.b64 [%0], %1;" :: "r"(mbar), "r"(count) : "memory");
}
__device__ __forceinline__ void mbar_expect_tx(uint32_t mbar, uint32_t bytes) {
    asm volatile("mbarrier.arrive.expect_tx.shared.b64 _, [%0], %1;"
                 :: "r"(mbar), "r"(bytes) : "memory");
}
__device__ __forceinline__ void mbar_arrive(uint32_t mbar) {
    asm volatile("mbarrier.arrive.shared.b64 _, [%0];" :: "r"(mbar) : "memory");
}
__device__ __forceinline__ void mbar_wait(uint32_t mbar, int phase) {
    asm volatile(
        "{\n\t.reg .pred P;\n\t"
        "W%=:\n\t"
        "mbarrier.try_wait.parity.acquire.cta.shared::cta.b64 P, [%0], %1, 0x989680;\n\t"
        "@!P bra W%=;\n\t"
        "}" :: "r"(mbar), "r"(phase) : "memory");
}
// Bulk async copy global->shared, completion via mbarrier tx bytes.
__device__ __forceinline__ void bulk_g2s(uint32_t dst, const void* src,
                                         uint32_t bytes, uint32_t mbar) {
    asm volatile(
        "cp.async.bulk.shared::cluster.global.mbarrier::complete_tx::bytes "
        "[%0], [%1], %2, [%3];"
        :: "r"(dst), "l"(src), "r"(bytes), "r"(mbar) : "memory");
}

__global__ void __launch_bounds__(NTHR)
mse_kernel(const float* __restrict__ in,
           const float* __restrict__ tg,
           float* __restrict__ out,
           int n) {
    __shared__ alignas(16) float4 s_in[STAGES][CHUNK_F4];
    __shared__ alignas(16) float4 s_tg[STAGES][CHUNK_F4];
    __shared__ alignas(8) uint64_t mb_full[STAGES];
    __shared__ alignas(8) uint64_t mb_empty[STAGES];

    const int tid = threadIdx.x;
    const int nchunk = n / CHUNK_F;          // full chunks per array
    int T = 0;                               // trips for this block
    if ((int)blockIdx.x < nchunk)
        T = (nchunk - (int)blockIdx.x + NBLK - 1) / NBLK;

    if (tid == 0) {
        #pragma unroll
        for (int s = 0; s < STAGES; s++) {
            mbar_init(smem_u32(&mb_full[s]), 1);        // expect_tx arrival
            mbar_init(smem_u32(&mb_empty[s]), NTHR);    // every thread arrives
        }
    }
    __syncthreads();

    // ── Prologue: fill up to STAGES stages ──
    if (tid == 0) {
        int pre = (T < STAGES) ? T : STAGES;
        for (int p = 0; p < pre; p++) {
            long long ci = (long long)blockIdx.x + (long long)p * NBLK;
            uint32_t mb = smem_u32(&mb_full[p]);
            mbar_expect_tx(mb, 2 * CHUNK_BYTES);
            bulk_g2s(smem_u32(&s_in[p][0]), (const char*)in + ci * CHUNK_BYTES,
                     CHUNK_BYTES, mb);
            bulk_g2s(smem_u32(&s_tg[p][0]), (const char*)tg + ci * CHUNK_BYTES,
                     CHUNK_BYTES, mb);
        }
    }

    float acc0 = 0.0f, acc1 = 0.0f;

    // ── Pipelined mainloop ──
    for (int t = 0; t < T; t++) {
        int s   = t % STAGES;
        int par = (t / STAGES) & 1;

        mbar_wait(smem_u32(&mb_full[s]), par);   // acquire: data visible

        float4 a0 = s_in[s][tid];
        float4 a1 = s_in[s][tid + NTHR];
        float4 b0 = s_tg[s][tid];
        float4 b1 = s_tg[s][tid + NTHR];
        float d;
        d = a0.x - b0.x; acc0 = fmaf(d, d, acc0);
        d = a0.y - b0.y; acc1 = fmaf(d, d, acc1);
        d = a0.z - b0.z; acc0 = fmaf(d, d, acc0);
        d = a0.w - b0.w; acc1 = fmaf(d, d, acc1);
        d = a1.x - b1.x; acc0 = fmaf(d, d, acc0);
        d = a1.y - b1.y; acc1 = fmaf(d, d, acc1);
        d = a1.z - b1.z; acc0 = fmaf(d, d, acc0);
        d = a1.w - b1.w; acc1 = fmaf(d, d, acc1);

        // Order our generic-proxy reads before the async-proxy TMA overwrite.
        asm volatile("fence.proxy.async.shared::cta;" ::: "memory");
        mbar_arrive(smem_u32(&mb_empty[s]));

        if (tid == 0 && t + STAGES < T) {
            // All NTHR arrivals for this trip complete phase `par`.
            mbar_wait(smem_u32(&mb_empty[s]), par);
            long long ci = (long long)blockIdx.x + (long long)(t + STAGES) * NBLK;
            uint32_t mb = smem_u32(&mb_full[s]);
            mbar_expect_tx(mb, 2 * CHUNK_BYTES);
            bulk_g2s(smem_u32(&s_in[s][0]), (const char*)in + ci * CHUNK_BYTES,
                     CHUNK_BYTES, mb);
            bulk_g2s(smem_u32(&s_tg[s][0]), (const char*)tg + ci * CHUNK_BYTES,
                     CHUNK_BYTES, mb);
        }
    }

    float acc = acc0 + acc1;

    // ── Warp + block reduction ──
    #pragma unroll
    for (int off = 16; off > 0; off >>= 1)
        acc += __shfl_xor_sync(0xFFFFFFFFu, acc, off);

    __shared__ float warp_sums[NTHR / 32];
    int lane = tid & 31;
    int wid  = tid >> 5;
    if (lane == 0) warp_sums[wid] = acc;
    __syncthreads();

    __shared__ bool is_last;
    if (wid == 0) {
        float v = (lane < NTHR / 32) ? warp_sums[lane] : 0.0f;
        #pragma unroll
        for (int off = 16; off > 0; off >>= 1)
            v += __shfl_xor_sync(0xFFFFFFFFu, v, off);
        if (lane == 0) {
            g_part[blockIdx.x] = v;
            __threadfence();
            unsigned old = atomicInc(&g_count, NBLK - 1);  // wraps -> replay-safe
            is_last = (old == NBLK - 1);
        }
    }
    __syncthreads();

    if (!is_last) return;

    // ── Last block: reduce partials in double + tail + finalize ──
    __threadfence();

    double s = 0.0;
    for (int k = tid; k < NBLK; k += NTHR)
        s += (double)g_part[k];

    #pragma unroll
    for (int off = 16; off > 0; off >>= 1)
        s += __shfl_xor_sync(0xFFFFFFFFu, s, off);

    __shared__ double dsums[NTHR / 32];
    if (lane == 0) dsums[wid] = s;
    __syncthreads();

    if (tid == 0) {
        double total = 0.0;
        #pragma unroll
        for (int w = 0; w < NTHR / 32; w++) total += dsums[w];

        // Scalar tail for elements not covered by full chunks (0 for N=32M).
        for (int k = nchunk * CHUNK_F; k < n; k++) {
            double dd = (double)in[k] - (double)tg[k];
            total += dd * dd;
        }

        // Element-0 conditional rescale, applied analytically.
        float d0 = fabsf(in[0] - tg[0]);
        bool hit = (d0 == 3.0f) || (d0 == 4.0f) || (d0 == 5.0f) || (d0 == 6.0f);
        float d0a = hit ? d0 * 0.8f : d0;
        total += (double)d0a * (double)d0a - (double)d0 * (double)d0;

        out[0] = (float)(total / (double)n);
    }
}

extern "C" void kernel_launch(void* const* d_in, const int* in_sizes, int n_in,
                              void* d_out, int out_size) {
    const float* in = (const float*)d_in[0];
    const float* tg = (const float*)d_in[1];
    float* out = (float*)d_out;
    int n = in_sizes[0];

    mse_kernel<<<NBLK, NTHR>>>(in, tg, out, n);
}